// round 1
// baseline (speedup 1.0000x reference)
#include <cuda_runtime.h>
#include <math.h>

#define BATCH 4
#define SLEN 2048
#define DM 2048
#define NHEAD 16
#define HS 128
#define EPROJ (3 * DM)

// Scratch (no allocations allowed): q in [B,H,S,hs] layout, attn_o in [B,S,D].
__device__ float g_q[(size_t)BATCH * NHEAD * SLEN * HS];
__device__ float g_attn[(size_t)BATCH * SLEN * DM];

// ---------------------------------------------------------------------------
// C = A * W^T + bias.  A [M,K] row-major, W [N,K] row-major (both K-contiguous).
// 128x128 tile, BK=16, 256 threads, 8x8 accumulators per thread.
// EPI==1: QKV scatter epilogue (q -> g_q, k/v -> d_out kv region)
// EPI==2: dense epilogue into C (A is g_attn)
// ---------------------------------------------------------------------------
template <int EPI>
__global__ __launch_bounds__(256) void gemm_nt_kernel(
    const float* __restrict__ Ain, const float* __restrict__ W,
    const float* __restrict__ bias, float* __restrict__ C,
    float* __restrict__ kout, float* __restrict__ vout, int K)
{
    const float* A = (EPI == 2) ? (const float*)g_attn : Ain;

    __shared__ float As[16][132];
    __shared__ float Bs[16][132];

    const int m0 = blockIdx.y * 128;
    const int n0 = blockIdx.x * 128;
    const int tid = threadIdx.x;
    const int ty = tid >> 4;   // 0..15
    const int tx = tid & 15;   // 0..15

    float acc[8][8];
#pragma unroll
    for (int i = 0; i < 8; i++)
#pragma unroll
        for (int j = 0; j < 8; j++) acc[i][j] = 0.f;

    const int lrow = tid >> 2;          // 0..63
    const int lk = (tid & 3) << 2;      // 0,4,8,12

    for (int k0 = 0; k0 < K; k0 += 16) {
#pragma unroll
        for (int ld = 0; ld < 2; ld++) {
            const int rr = lrow + ld * 64;
            float4 a4 = *(const float4*)(A + (size_t)(m0 + rr) * K + (k0 + lk));
            As[lk + 0][rr] = a4.x; As[lk + 1][rr] = a4.y;
            As[lk + 2][rr] = a4.z; As[lk + 3][rr] = a4.w;
            float4 b4 = *(const float4*)(W + (size_t)(n0 + rr) * K + (k0 + lk));
            Bs[lk + 0][rr] = b4.x; Bs[lk + 1][rr] = b4.y;
            Bs[lk + 2][rr] = b4.z; Bs[lk + 3][rr] = b4.w;
        }
        __syncthreads();
#pragma unroll
        for (int k = 0; k < 16; k++) {
            float a[8], b[8];
#pragma unroll
            for (int i = 0; i < 8; i++) a[i] = As[k][ty * 8 + i];
#pragma unroll
            for (int j = 0; j < 8; j++) b[j] = Bs[k][tx * 8 + j];
#pragma unroll
            for (int i = 0; i < 8; i++)
#pragma unroll
                for (int j = 0; j < 8; j++)
                    acc[i][j] = fmaf(a[i], b[j], acc[i][j]);
        }
        __syncthreads();
    }

    if (EPI == 1) {
        // e = h*384 + r ; r<128 -> q, r<256 -> k, else v. m = b*SLEN + s.
        const int m_base = m0 + ty * 8;
#pragma unroll
        for (int j = 0; j < 8; j++) {
            const int e = n0 + tx * 8 + j;
            const int h = e / 384;
            const int r = e - h * 384;
            const float bv = bias[e];
            float* dstbase;
            int roff;
            if (r < 128)       { dstbase = g_q;  roff = r; }
            else if (r < 256)  { dstbase = kout; roff = r - 128; }
            else               { dstbase = vout; roff = r - 256; }
#pragma unroll
            for (int i = 0; i < 8; i++) {
                const int m = m_base + i;
                const int b = m >> 11;       // /SLEN
                const int s = m & 2047;
                dstbase[(((size_t)(b * NHEAD + h)) * SLEN + s) * HS + roff] =
                    acc[i][j] + bv;
            }
        }
    } else {
        const float4 bias0 = *(const float4*)(bias + n0 + tx * 8);
        const float4 bias1 = *(const float4*)(bias + n0 + tx * 8 + 4);
#pragma unroll
        for (int i = 0; i < 8; i++) {
            const int m = m0 + ty * 8 + i;
            float* dst = C + (size_t)m * DM + n0 + tx * 8;
            float4 r0 = make_float4(acc[i][0] + bias0.x, acc[i][1] + bias0.y,
                                    acc[i][2] + bias0.z, acc[i][3] + bias0.w);
            float4 r1 = make_float4(acc[i][4] + bias1.x, acc[i][5] + bias1.y,
                                    acc[i][6] + bias1.z, acc[i][7] + bias1.w);
            *(float4*)dst = r0;
            *(float4*)(dst + 4) = r1;
        }
    }
}

// ---------------------------------------------------------------------------
// Flash attention, causal. One block = (q-tile of 64 rows, one b*H+h).
// smem: Qs[64][128], KV[64][128] (K then overwritten by V), Ss[64][65], stats.
// ---------------------------------------------------------------------------
#define ATTN_SMEM_FLOATS (64 * 128 + 64 * 128 + 64 * 65 + 192)
#define ATTN_SMEM_BYTES (ATTN_SMEM_FLOATS * 4)

__global__ __launch_bounds__(256) void attn_kernel(
    const float* __restrict__ Kg, const float* __restrict__ Vg)
{
    extern __shared__ float sm[];
    float* Qs  = sm;              // 64*128
    float* KVs = sm + 8192;       // 64*128
    float* Ss  = sm + 16384;      // 64*65
    float* m_s = Ss + 64 * 65;
    float* l_s = m_s + 64;
    float* a_s = l_s + 64;

    const int qt  = blockIdx.x;   // 0..31
    const int bh  = blockIdx.y;   // 0..63
    const int tid = threadIdx.x;
    const int tr  = tid >> 4;     // 0..15
    const int tc  = tid & 15;     // 0..15

    const float* Qb = g_q + (size_t)bh * SLEN * HS + (size_t)qt * 64 * HS;
    const float* Kb = Kg + (size_t)bh * SLEN * HS;
    const float* Vb = Vg + (size_t)bh * SLEN * HS;

    const float scale = 0.08838834764831845f;  // 1/sqrt(128)
    for (int i = tid; i < 64 * 32; i += 256) {
        float4 v = ((const float4*)Qb)[i];
        v.x *= scale; v.y *= scale; v.z *= scale; v.w *= scale;
        ((float4*)Qs)[i] = v;
    }
    if (tid < 64) { m_s[tid] = -INFINITY; l_s[tid] = 0.f; }

    float o[4][8];
#pragma unroll
    for (int i = 0; i < 4; i++)
#pragma unroll
        for (int j = 0; j < 8; j++) o[i][j] = 0.f;

    for (int kt = 0; kt <= qt; kt++) {
        __syncthreads();  // Q ready / previous PV done with KVs
        const float4* Kt = (const float4*)(Kb + (size_t)kt * 64 * HS);
        for (int i = tid; i < 64 * 32; i += 256) ((float4*)KVs)[i] = Kt[i];
        __syncthreads();

        float s4[4][4];
#pragma unroll
        for (int i = 0; i < 4; i++)
#pragma unroll
            for (int j = 0; j < 4; j++) s4[i][j] = 0.f;

#pragma unroll 4
        for (int d = 0; d < 128; d += 4) {
            float4 qv[4], kv[4];
#pragma unroll
            for (int i = 0; i < 4; i++)
                qv[i] = *(const float4*)(Qs + (tr * 4 + i) * 128 + d);
#pragma unroll
            for (int j = 0; j < 4; j++)
                kv[j] = *(const float4*)(KVs + (tc * 4 + j) * 128 + d);
#pragma unroll
            for (int i = 0; i < 4; i++)
#pragma unroll
                for (int j = 0; j < 4; j++) {
                    s4[i][j] = fmaf(qv[i].x, kv[j].x, s4[i][j]);
                    s4[i][j] = fmaf(qv[i].y, kv[j].y, s4[i][j]);
                    s4[i][j] = fmaf(qv[i].z, kv[j].z, s4[i][j]);
                    s4[i][j] = fmaf(qv[i].w, kv[j].w, s4[i][j]);
                }
        }

        const bool diag = (kt == qt);
#pragma unroll
        for (int i = 0; i < 4; i++)
#pragma unroll
            for (int j = 0; j < 4; j++) {
                const int r = tr * 4 + i, c = tc * 4 + j;
                float v = s4[i][j];
                if (diag && c > r) v = -INFINITY;  // exp -> 0, same as MIN_FP16
                Ss[r * 65 + c] = v;
            }
        __syncthreads();

        // Overwrite KVs with V tile (K no longer needed)
        const float4* Vt = (const float4*)(Vb + (size_t)kt * 64 * HS);
        for (int i = tid; i < 64 * 32; i += 256) ((float4*)KVs)[i] = Vt[i];

        // Streaming softmax row pass
        if (tid < 64) {
            const int r = tid;
            const float mold = m_s[r];
            float mnew = mold;
#pragma unroll 8
            for (int c = 0; c < 64; c++) mnew = fmaxf(mnew, Ss[r * 65 + c]);
            const float alpha = __expf(mold - mnew);
            float lsum = 0.f;
#pragma unroll 8
            for (int c = 0; c < 64; c++) {
                const float p = __expf(Ss[r * 65 + c] - mnew);
                Ss[r * 65 + c] = p;
                lsum += p;
            }
            l_s[r] = l_s[r] * alpha + lsum;
            m_s[r] = mnew;
            a_s[r] = alpha;
        }
        __syncthreads();

        // o = o*alpha + P*V   (rows tr*4..+3, cols tc*8..+7)
#pragma unroll
        for (int i = 0; i < 4; i++) {
            const float al = a_s[tr * 4 + i];
#pragma unroll
            for (int j = 0; j < 8; j++) o[i][j] *= al;
        }
#pragma unroll 4
        for (int k = 0; k < 64; k++) {
            const float4 v0 = *(const float4*)(KVs + k * 128 + tc * 8);
            const float4 v1 = *(const float4*)(KVs + k * 128 + tc * 8 + 4);
#pragma unroll
            for (int i = 0; i < 4; i++) {
                const float p = Ss[(tr * 4 + i) * 65 + k];
                o[i][0] = fmaf(p, v0.x, o[i][0]);
                o[i][1] = fmaf(p, v0.y, o[i][1]);
                o[i][2] = fmaf(p, v0.z, o[i][2]);
                o[i][3] = fmaf(p, v0.w, o[i][3]);
                o[i][4] = fmaf(p, v1.x, o[i][4]);
                o[i][5] = fmaf(p, v1.y, o[i][5]);
                o[i][6] = fmaf(p, v1.z, o[i][6]);
                o[i][7] = fmaf(p, v1.w, o[i][7]);
            }
        }
    }

    // Write attn_o into [B,S,D] layout (D index = h*HS + d) for the FF GEMM.
    const int b = bh >> 4, h = bh & 15;
#pragma unroll
    for (int i = 0; i < 4; i++) {
        const int r = tr * 4 + i;
        const float inv = 1.f / l_s[r];
        float* dst = g_attn + ((size_t)(b * SLEN + qt * 64 + r)) * DM + h * HS + tc * 8;
        float4 w0 = make_float4(o[i][0] * inv, o[i][1] * inv, o[i][2] * inv, o[i][3] * inv);
        float4 w1 = make_float4(o[i][4] * inv, o[i][5] * inv, o[i][6] * inv, o[i][7] * inv);
        *(float4*)dst = w0;
        *(float4*)(dst + 4) = w1;
    }
}

// ---------------------------------------------------------------------------
extern "C" void kernel_launch(void* const* d_in, const int* in_sizes, int n_in,
                              void* d_out, int out_size)
{
    const float* x      = (const float*)d_in[0];
    const float* w_proj = (const float*)d_in[1];
    const float* b_proj = (const float*)d_in[2];
    const float* w_ff   = (const float*)d_in[3];
    const float* b_ff   = (const float*)d_in[4];

    float* out = (float*)d_out;
    float* ff   = out;                                        // [B,S,D]
    float* kout = out + (size_t)BATCH * SLEN * DM;            // next_prefix_kv[0]
    float* vout = kout + (size_t)BATCH * NHEAD * SLEN * HS;   // next_prefix_kv[1]

    cudaFuncSetAttribute(attn_kernel,
                         cudaFuncAttributeMaxDynamicSharedMemorySize,
                         ATTN_SMEM_BYTES);

    // 1) QKV projection: q -> g_q, k/v -> d_out kv region
    gemm_nt_kernel<1><<<dim3(EPROJ / 128, (BATCH * SLEN) / 128), 256>>>(
        x, w_proj, b_proj, (float*)nullptr, kout, vout, DM);

    // 2) Causal flash attention -> g_attn [B,S,D]
    attn_kernel<<<dim3(SLEN / 64, BATCH * NHEAD), 256, ATTN_SMEM_BYTES>>>(kout, vout);

    // 3) FF projection -> ff output
    gemm_nt_kernel<2><<<dim3(DM / 128, (BATCH * SLEN) / 128), 256>>>(
        (const float*)nullptr, w_ff, b_ff, ff, (float*)nullptr, (float*)nullptr, DM);
}

// round 3
// speedup vs baseline: 1.4300x; 1.4300x over previous
#include <cuda_runtime.h>
#include <cuda_bf16.h>
#include <math.h>
#include <stdint.h>

#define BATCH 4
#define SLEN 2048
#define DM 2048
#define NHEAD 16
#define HS 128
#define EPROJ (3 * DM)

// Scratch (no allocations allowed)
__device__ float g_q[(size_t)BATCH * NHEAD * SLEN * HS];
__device__ float g_attn[(size_t)BATCH * SLEN * DM];

// ---------------------------------------------------------------------------
// helpers (non-arch-specific PTX only: ldmatrix sm_75+, mma.sync bf16 sm_80+)
// ---------------------------------------------------------------------------
__device__ __forceinline__ uint32_t smem_u32(const void* p) {
    uint32_t a;
    asm("{ .reg .u64 t; cvta.to.shared.u64 t, %1; cvt.u32.u64 %0, t; }"
        : "=r"(a) : "l"(p));
    return a;
}

__device__ __forceinline__ void ldm_x4(uint32_t* r, uint32_t addr) {
    asm volatile("ldmatrix.sync.aligned.m8n8.x4.shared.b16 {%0,%1,%2,%3}, [%4];"
                 : "=r"(r[0]), "=r"(r[1]), "=r"(r[2]), "=r"(r[3]) : "r"(addr));
}

__device__ __forceinline__ void mma_bf16(float* c, const uint32_t* a,
                                         const uint32_t* b) {
    asm volatile(
        "mma.sync.aligned.m16n8k16.row.col.f32.bf16.bf16.f32 "
        "{%0,%1,%2,%3}, {%4,%5,%6,%7}, {%8,%9}, {%0,%1,%2,%3};"
        : "+f"(c[0]), "+f"(c[1]), "+f"(c[2]), "+f"(c[3])
        : "r"(a[0]), "r"(a[1]), "r"(a[2]), "r"(a[3]), "r"(b[0]), "r"(b[1]));
}

// fp32x4 -> hi/lo bf16x4 (2-way split)
__device__ __forceinline__ void split4(float4 v, uint2& hi, uint2& lo) {
    __nv_bfloat162 h01 = __floats2bfloat162_rn(v.x, v.y);
    __nv_bfloat162 h23 = __floats2bfloat162_rn(v.z, v.w);
    uint32_t u01 = *(uint32_t*)&h01, u23 = *(uint32_t*)&h23;
    float fx = __uint_as_float(u01 << 16);
    float fy = __uint_as_float(u01 & 0xffff0000u);
    float fz = __uint_as_float(u23 << 16);
    float fw = __uint_as_float(u23 & 0xffff0000u);
    __nv_bfloat162 l01 = __floats2bfloat162_rn(v.x - fx, v.y - fy);
    __nv_bfloat162 l23 = __floats2bfloat162_rn(v.z - fz, v.w - fw);
    hi = make_uint2(u01, u23);
    lo = make_uint2(*(uint32_t*)&l01, *(uint32_t*)&l23);
}

// ---------------------------------------------------------------------------
// mma.sync bf16-split GEMM: C = A * W^T + bias
// A [M,K] fp32 row-major, W [N,K] fp32 row-major, K=2048.
// CTA 128x128, 8 warps (2 M x 4 N), warp tile 64x32, BK=32.
// EPI==1: QKV scatter epilogue, EPI==2: dense C (A = g_attn).
// ---------------------------------------------------------------------------
#define PITCH 40            // bf16 elements per smem row (80B, conflict-free)
#define TILE_E (128 * PITCH)
#define AHI 0
#define ALO TILE_E
#define WHI (2 * TILE_E)
#define WLO (3 * TILE_E)

template <int EPI>
__global__ __launch_bounds__(256) void gemm_mma_kernel(
    const float* __restrict__ Ain, const float* __restrict__ W,
    const float* __restrict__ bias, float* __restrict__ C,
    float* __restrict__ kout, float* __restrict__ vout)
{
    __shared__ __align__(16) __nv_bfloat16 sm_bf[4 * TILE_E];  // 40960 B

    const float* A = (EPI == 2) ? (const float*)g_attn : Ain;
    const int K = 2048;
    const int tid = threadIdx.x;
    const int wid = tid >> 5;
    const int lid = tid & 31;
    const int m0 = blockIdx.y * 128;
    const int n0 = blockIdx.x * 128;
    const int warpM = wid >> 2;   // 0..1
    const int warpN = wid & 3;    // 0..3

    const uint32_t sbase = smem_u32(sm_bf);

    // ldmatrix lane addressing
    const int q = lid >> 3, rr = lid & 7;
    // A: mat q: rows (q&1)*8+rr, k-chunk (q>>1)*8
    const uint32_t aAddr = sbase +
        (uint32_t)(((warpM * 64 + (q & 1) * 8 + rr) * PITCH + (q >> 1) * 8) * 2);
    // B: mat q: n rows (q>>1)*8+rr, k-chunk (q&1)*8
    const uint32_t bAddr = sbase +
        (uint32_t)(((warpN * 32 + (q >> 1) * 8 + rr) * PITCH + (q & 1) * 8) * 2);

    float acc[4][4][4];
#pragma unroll
    for (int i = 0; i < 4; i++)
#pragma unroll
        for (int j = 0; j < 4; j++)
#pragma unroll
            for (int r = 0; r < 4; r++) acc[i][j][r] = 0.f;

    // staging addressing: row = tid>>1 (0..127), 16 cols per thread
    const int srow = tid >> 1;
    const int scol = (tid & 1) << 4;
    const float* Aptr = A + (size_t)(m0 + srow) * K + scol;
    const float* Wptr = W + (size_t)(n0 + srow) * K + scol;
    const uint32_t sto = (uint32_t)(srow * PITCH + scol);  // element offset

    float4 va[4], vw[4];
#pragma unroll
    for (int i = 0; i < 4; i++) {
        va[i] = *(const float4*)(Aptr + i * 4);
        vw[i] = *(const float4*)(Wptr + i * 4);
    }

    for (int c = 0; c < 64; c++) {
        __syncthreads();
#pragma unroll
        for (int i = 0; i < 4; i++) {
            uint2 hi, lo;
            split4(va[i], hi, lo);
            *(uint2*)((char*)sm_bf + (size_t)(AHI + sto + i * 4) * 2) = hi;
            *(uint2*)((char*)sm_bf + (size_t)(ALO + sto + i * 4) * 2) = lo;
            split4(vw[i], hi, lo);
            *(uint2*)((char*)sm_bf + (size_t)(WHI + sto + i * 4) * 2) = hi;
            *(uint2*)((char*)sm_bf + (size_t)(WLO + sto + i * 4) * 2) = lo;
        }
        if (c < 63) {
            const float* ap = Aptr + (c + 1) * 32;
            const float* wp = Wptr + (c + 1) * 32;
#pragma unroll
            for (int i = 0; i < 4; i++) {
                va[i] = *(const float4*)(ap + i * 4);
                vw[i] = *(const float4*)(wp + i * 4);
            }
        }
        __syncthreads();

#pragma unroll
        for (int ks = 0; ks < 2; ks++) {
            const uint32_t kb = (uint32_t)(ks * 16 * 2);
            uint32_t ah[4][4], al[4][4], bh[2][4], bl[2][4];
#pragma unroll
            for (int mi = 0; mi < 4; mi++) {
                const uint32_t off = (uint32_t)(mi * 16 * PITCH * 2) + kb;
                ldm_x4(ah[mi], aAddr + AHI * 2 + off);
                ldm_x4(al[mi], aAddr + ALO * 2 + off);
            }
#pragma unroll
            for (int pj = 0; pj < 2; pj++) {
                const uint32_t off = (uint32_t)(pj * 16 * PITCH * 2) + kb;
                ldm_x4(bh[pj], bAddr + WHI * 2 + off);
                ldm_x4(bl[pj], bAddr + WLO * 2 + off);
            }
#pragma unroll
            for (int mi = 0; mi < 4; mi++)
#pragma unroll
                for (int nj = 0; nj < 4; nj++) {
                    const uint32_t* bhp = &bh[nj >> 1][(nj & 1) * 2];
                    const uint32_t* blp = &bl[nj >> 1][(nj & 1) * 2];
                    mma_bf16(acc[mi][nj], ah[mi], bhp);
                    mma_bf16(acc[mi][nj], al[mi], bhp);
                    mma_bf16(acc[mi][nj], ah[mi], blp);
                }
        }
    }

    // Epilogue
    const int t4 = lid >> 2;
    const int t2 = (lid & 3) << 1;
#pragma unroll
    for (int mi = 0; mi < 4; mi++) {
        const int mrow = m0 + warpM * 64 + mi * 16 + t4;
        float *d0, *d1;
        if (EPI == 1) {
            const int seg = n0 >> 7;
            const int h = (int)((unsigned)seg / 3u);
            const int which = seg - h * 3;
            float* base = (which == 0) ? g_q : ((which == 1) ? kout : vout);
            const int b0i = mrow >> 11, s0i = mrow & 2047;
            const int b1i = (mrow + 8) >> 11, s1i = (mrow + 8) & 2047;
            d0 = base + (((size_t)(b0i * NHEAD + h)) * SLEN + s0i) * HS;
            d1 = base + (((size_t)(b1i * NHEAD + h)) * SLEN + s1i) * HS;
        } else {
            d0 = C + (size_t)mrow * DM + n0;
            d1 = C + (size_t)(mrow + 8) * DM + n0;
        }
#pragma unroll
        for (int nj = 0; nj < 4; nj++) {
            const int col = warpN * 32 + nj * 8 + t2;
            const float2 bb = *(const float2*)(bias + n0 + col);
            float2 r0 = make_float2(acc[mi][nj][0] + bb.x, acc[mi][nj][1] + bb.y);
            float2 r1 = make_float2(acc[mi][nj][2] + bb.x, acc[mi][nj][3] + bb.y);
            *(float2*)(d0 + col) = r0;
            *(float2*)(d1 + col) = r1;
        }
    }
}

// ---------------------------------------------------------------------------
// Flash attention (fp32 SIMT), causal — unchanged.
// ---------------------------------------------------------------------------
#define ATTN_SMEM_FLOATS (64 * 128 + 64 * 128 + 64 * 65 + 192)
#define ATTN_SMEM_BYTES (ATTN_SMEM_FLOATS * 4)

__global__ __launch_bounds__(256) void attn_kernel(
    const float* __restrict__ Kg, const float* __restrict__ Vg)
{
    extern __shared__ float sm[];
    float* Qs  = sm;
    float* KVs = sm + 8192;
    float* Ss  = sm + 16384;
    float* m_s = Ss + 64 * 65;
    float* l_s = m_s + 64;
    float* a_s = l_s + 64;

    const int qt  = blockIdx.x;
    const int bh  = blockIdx.y;
    const int tid = threadIdx.x;
    const int tr  = tid >> 4;
    const int tc  = tid & 15;

    const float* Qb = g_q + (size_t)bh * SLEN * HS + (size_t)qt * 64 * HS;
    const float* Kb = Kg + (size_t)bh * SLEN * HS;
    const float* Vb = Vg + (size_t)bh * SLEN * HS;

    const float scale = 0.08838834764831845f;
    for (int i = tid; i < 64 * 32; i += 256) {
        float4 v = ((const float4*)Qb)[i];
        v.x *= scale; v.y *= scale; v.z *= scale; v.w *= scale;
        ((float4*)Qs)[i] = v;
    }
    if (tid < 64) { m_s[tid] = -INFINITY; l_s[tid] = 0.f; }

    float o[4][8];
#pragma unroll
    for (int i = 0; i < 4; i++)
#pragma unroll
        for (int j = 0; j < 8; j++) o[i][j] = 0.f;

    for (int kt = 0; kt <= qt; kt++) {
        __syncthreads();
        const float4* Kt = (const float4*)(Kb + (size_t)kt * 64 * HS);
        for (int i = tid; i < 64 * 32; i += 256) ((float4*)KVs)[i] = Kt[i];
        __syncthreads();

        float s4[4][4];
#pragma unroll
        for (int i = 0; i < 4; i++)
#pragma unroll
            for (int j = 0; j < 4; j++) s4[i][j] = 0.f;

#pragma unroll 4
        for (int d = 0; d < 128; d += 4) {
            float4 qv[4], kv[4];
#pragma unroll
            for (int i = 0; i < 4; i++)
                qv[i] = *(const float4*)(Qs + (tr * 4 + i) * 128 + d);
#pragma unroll
            for (int j = 0; j < 4; j++)
                kv[j] = *(const float4*)(KVs + (tc * 4 + j) * 128 + d);
#pragma unroll
            for (int i = 0; i < 4; i++)
#pragma unroll
                for (int j = 0; j < 4; j++) {
                    s4[i][j] = fmaf(qv[i].x, kv[j].x, s4[i][j]);
                    s4[i][j] = fmaf(qv[i].y, kv[j].y, s4[i][j]);
                    s4[i][j] = fmaf(qv[i].z, kv[j].z, s4[i][j]);
                    s4[i][j] = fmaf(qv[i].w, kv[j].w, s4[i][j]);
                }
        }

        const bool diag = (kt == qt);
#pragma unroll
        for (int i = 0; i < 4; i++)
#pragma unroll
            for (int j = 0; j < 4; j++) {
                const int r = tr * 4 + i, c = tc * 4 + j;
                float v = s4[i][j];
                if (diag && c > r) v = -INFINITY;
                Ss[r * 65 + c] = v;
            }
        __syncthreads();

        const float4* Vt = (const float4*)(Vb + (size_t)kt * 64 * HS);
        for (int i = tid; i < 64 * 32; i += 256) ((float4*)KVs)[i] = Vt[i];

        if (tid < 64) {
            const int r = tid;
            const float mold = m_s[r];
            float mnew = mold;
#pragma unroll 8
            for (int c = 0; c < 64; c++) mnew = fmaxf(mnew, Ss[r * 65 + c]);
            const float alpha = __expf(mold - mnew);
            float lsum = 0.f;
#pragma unroll 8
            for (int c = 0; c < 64; c++) {
                const float p = __expf(Ss[r * 65 + c] - mnew);
                Ss[r * 65 + c] = p;
                lsum += p;
            }
            l_s[r] = l_s[r] * alpha + lsum;
            m_s[r] = mnew;
            a_s[r] = alpha;
        }
        __syncthreads();

#pragma unroll
        for (int i = 0; i < 4; i++) {
            const float al = a_s[tr * 4 + i];
#pragma unroll
            for (int j = 0; j < 8; j++) o[i][j] *= al;
        }
#pragma unroll 4
        for (int k = 0; k < 64; k++) {
            const float4 v0 = *(const float4*)(KVs + k * 128 + tc * 8);
            const float4 v1 = *(const float4*)(KVs + k * 128 + tc * 8 + 4);
#pragma unroll
            for (int i = 0; i < 4; i++) {
                const float p = Ss[(tr * 4 + i) * 65 + k];
                o[i][0] = fmaf(p, v0.x, o[i][0]);
                o[i][1] = fmaf(p, v0.y, o[i][1]);
                o[i][2] = fmaf(p, v0.z, o[i][2]);
                o[i][3] = fmaf(p, v0.w, o[i][3]);
                o[i][4] = fmaf(p, v1.x, o[i][4]);
                o[i][5] = fmaf(p, v1.y, o[i][5]);
                o[i][6] = fmaf(p, v1.z, o[i][6]);
                o[i][7] = fmaf(p, v1.w, o[i][7]);
            }
        }
    }

    const int b = bh >> 4, h = bh & 15;
#pragma unroll
    for (int i = 0; i < 4; i++) {
        const int r = tr * 4 + i;
        const float inv = 1.f / l_s[r];
        float* dst = g_attn + ((size_t)(b * SLEN + qt * 64 + r)) * DM + h * HS + tc * 8;
        float4 w0 = make_float4(o[i][0] * inv, o[i][1] * inv, o[i][2] * inv, o[i][3] * inv);
        float4 w1 = make_float4(o[i][4] * inv, o[i][5] * inv, o[i][6] * inv, o[i][7] * inv);
        *(float4*)dst = w0;
        *(float4*)(dst + 4) = w1;
    }
}

// ---------------------------------------------------------------------------
extern "C" void kernel_launch(void* const* d_in, const int* in_sizes, int n_in,
                              void* d_out, int out_size)
{
    const float* x      = (const float*)d_in[0];
    const float* w_proj = (const float*)d_in[1];
    const float* b_proj = (const float*)d_in[2];
    const float* w_ff   = (const float*)d_in[3];
    const float* b_ff   = (const float*)d_in[4];

    float* out = (float*)d_out;
    float* ff   = out;                                        // [B,S,D]
    float* kout = out + (size_t)BATCH * SLEN * DM;            // next_prefix_kv[0]
    float* vout = kout + (size_t)BATCH * NHEAD * SLEN * HS;   // next_prefix_kv[1]

    cudaFuncSetAttribute(attn_kernel,
                         cudaFuncAttributeMaxDynamicSharedMemorySize, ATTN_SMEM_BYTES);

    // 1) QKV projection (mma.sync bf16-split): q -> g_q, k/v -> d_out kv region
    gemm_mma_kernel<1><<<dim3(EPROJ / 128, (BATCH * SLEN) / 128), 256>>>(
        x, w_proj, b_proj, (float*)nullptr, kout, vout);

    // 2) Causal flash attention -> g_attn [B,S,D]
    attn_kernel<<<dim3(SLEN / 64, BATCH * NHEAD), 256, ATTN_SMEM_BYTES>>>(kout, vout);

    // 3) FF projection (mma.sync bf16-split) -> ff output
    gemm_mma_kernel<2><<<dim3(DM / 128, (BATCH * SLEN) / 128), 256>>>(
        (const float*)nullptr, w_ff, b_ff, ff, (float*)nullptr, (float*)nullptr);
}